// round 8
// baseline (speedup 1.0000x reference)
#include <cuda_runtime.h>

// ---------------- problem constants ----------------
#define N_NODES  50000
#define N_EDGES  640000
#define N_GRAPHS 64
#define IN_DIM   128
#define HID      256
#define HID2     128   // HID/2
#define OUT_DIM  4

// ---------------- scratch (static device arrays; no allocation) ----------------
// RULE: these symbols are ONLY referenced inside device code; never passed as
// kernel arguments from host (host shadow address + ATS = silent wrong buffer).
__device__ float  g_dinv[N_NODES];                 // deg -> rsqrt(deg)
__device__ float4 g_agg1[N_NODES * (IN_DIM / 4)];  // aggregated x      [N,128]
__device__ float  g_h1 [N_NODES * HID];            // relu(agg1@W1+b1)  [N,256]
__device__ float4 g_m2  [N_NODES * (HID2 / 4)];    // h1@W2             [N,128]
__device__ float4 g_agg2[N_NODES * (HID2 / 4)];    // aggregated m2     [N,128]
__device__ float  g_pool[N_GRAPHS * HID2];         // per-graph sums
__device__ float  g_cnt [N_GRAPHS];                // per-graph counts
__device__ int    g_idx64;                         // 1 if index arrays are int64

// ---------------- helpers ----------------
__device__ __forceinline__ void red_add_v4(float* addr, float4 v) {
    asm volatile("red.global.add.v4.f32 [%0], {%1,%2,%3,%4};"
                 :: "l"(addr), "f"(v.x), "f"(v.y), "f"(v.z), "f"(v.w)
                 : "memory");
}

__device__ __forceinline__ int get_idx(const void* p, int i, int is64) {
    long long v;
    if (is64) v = __ldg(((const long long*)p) + i);
    else      v = __ldg(((const int*)p) + i);
    return (int)v;
}

// packed fp32 FMA: d = a*b + d (lane-wise on 2 floats in a 64-bit reg pair)
__device__ __forceinline__ void ffma2(unsigned long long& d,
                                      unsigned long long a, unsigned long long b) {
    asm volatile("fma.rn.f32x2 %0, %1, %2, %0;" : "+l"(d) : "l"(a), "l"(b));
}

// ---------------- index dtype detection ----------------
__global__ void k_detect(const int* p) {
    int lane = threadIdx.x;
    int nz = 0;
    for (int i = lane; i < 4096; i += 32)
        if (p[2 * i + 1] != 0) nz = 1;
    unsigned m = __ballot_sync(0xffffffffu, nz);
    if (lane == 0) g_idx64 = (m == 0u) ? 1 : 0;
}

// ---------------- degree / norm ----------------
__global__ void k_deg_init() {
    int i = blockIdx.x * blockDim.x + threadIdx.x;
    if (i < N_NODES) g_dinv[i] = 1.0f;     // +1 self loop
}

__global__ void k_deg_count(const void* __restrict__ dst) {
    int e = blockIdx.x * blockDim.x + threadIdx.x;
    if (e < N_EDGES) {
        int d = get_idx(dst, e, g_idx64);
        if ((unsigned)d < (unsigned)N_NODES) atomicAdd(&g_dinv[d], 1.0f);
    }
}

__global__ void k_rsqrt() {
    int i = blockIdx.x * blockDim.x + threadIdx.x;
    if (i < N_NODES) g_dinv[i] = rsqrtf(g_dinv[i]);
}

// ---------------- aggregation init: agg = feat * dinv^2 (self-loop term) ----------------
__global__ void k_init_agg1(const float4* __restrict__ x) {
    int t = blockIdx.x * blockDim.x + threadIdx.x;     // node*32 + j
    if (t >= N_NODES * 32) return;
    int node = t >> 5;
    float di = g_dinv[node];
    float s = di * di;
    float4 v = x[t];
    v.x *= s; v.y *= s; v.z *= s; v.w *= s;
    g_agg1[t] = v;
}

__global__ void k_init_agg2() {
    int t = blockIdx.x * blockDim.x + threadIdx.x;
    if (t >= N_NODES * 32) return;
    int node = t >> 5;
    float di = g_dinv[node];
    float s = di * di;
    float4 v = g_m2[t];
    v.x *= s; v.y *= s; v.z *= s; v.w *= s;
    g_agg2[t] = v;
}

// ---------------- edge scatter: agg[dst] += feat[src]*dinv[s]*dinv[d] ----------------
__global__ void k_edge1(const float4* __restrict__ x,
                        const void* __restrict__ src, const void* __restrict__ dst) {
    int t = blockIdx.x * blockDim.x + threadIdx.x;
    int e = t >> 5;
    if (e >= N_EDGES) return;
    int is64 = g_idx64;
    int j = t & 31;
    int s = get_idx(src, e, is64);
    int d = get_idx(dst, e, is64);
    if ((unsigned)s >= (unsigned)N_NODES || (unsigned)d >= (unsigned)N_NODES) return;
    float norm = g_dinv[s] * g_dinv[d];
    float4 v = x[(size_t)s * 32 + j];
    v.x *= norm; v.y *= norm; v.z *= norm; v.w *= norm;
    red_add_v4((float*)(g_agg1 + (size_t)d * 32 + j), v);
}

__global__ void k_edge2(const void* __restrict__ src, const void* __restrict__ dst) {
    int t = blockIdx.x * blockDim.x + threadIdx.x;
    int e = t >> 5;
    if (e >= N_EDGES) return;
    int is64 = g_idx64;
    int j = t & 31;
    int s = get_idx(src, e, is64);
    int d = get_idx(dst, e, is64);
    if ((unsigned)s >= (unsigned)N_NODES || (unsigned)d >= (unsigned)N_NODES) return;
    float norm = g_dinv[s] * g_dinv[d];
    float4 v = g_m2[(size_t)s * 32 + j];
    v.x *= norm; v.y *= norm; v.z *= norm; v.w *= norm;
    red_add_v4((float*)(g_agg2 + (size_t)d * 32 + j), v);
}

// ---------------- SGEMM with packed fp32 (fma.rn.f32x2) ----------------
// C[M,N] = A[M,K] @ B[K,N] (+bias, relu). BM=BN=128, BK=8, 256 threads,
// 8x8 microtile per thread held as 8x4 f32x2 accumulators.
// A tile stored DUPLICATED in shared (each value twice, consecutively) so the
// broadcast operand of FFMA2 comes straight from one LDS.64 (no MOV-dup).
template <int KDIM, int NDIM, bool RELU_BIAS>
__device__ __forceinline__ void sgemm_body(const float* __restrict__ A,
                                           const float* __restrict__ B,
                                           const float* __restrict__ bias,
                                           float* __restrict__ C) {
    constexpr int BM = 128, BN = 128, BK = 8;
    __shared__ float As2[BK][2 * BM];  // duplicated A tile (transposed), 8KB
    __shared__ float Bs [BK][BN];      // B tile, 4KB

    const int t    = threadIdx.x;             // 0..255
    const int cRow = blockIdx.y * BM;
    const int cCol = blockIdx.x * BN;
    const int tx   = t & 15;                   // col group (8 cols each)
    const int ty   = t >> 4;                   // row group (8 rows each)

    const int arow = cRow + (t >> 1);
    const int acol = (t & 1) * 4;
    const int brow = t >> 5;
    const int bcol = (t & 31) * 4;

    unsigned long long acc[8][4];              // acc[i][j2] = pair (j=2*j2, 2*j2+1)
    #pragma unroll
    for (int i = 0; i < 8; i++)
        #pragma unroll
        for (int j = 0; j < 4; j++) acc[i][j] = 0ull;

    for (int k0 = 0; k0 < KDIM; k0 += BK) {
        float4 av = make_float4(0.f, 0.f, 0.f, 0.f);
        if (arow < N_NODES)
            av = *(const float4*)(A + (size_t)arow * KDIM + k0 + acol);
        int m2 = (t >> 1) * 2;                 // duplicated index base
        As2[acol + 0][m2] = av.x; As2[acol + 0][m2 + 1] = av.x;
        As2[acol + 1][m2] = av.y; As2[acol + 1][m2 + 1] = av.y;
        As2[acol + 2][m2] = av.z; As2[acol + 2][m2 + 1] = av.z;
        As2[acol + 3][m2] = av.w; As2[acol + 3][m2 + 1] = av.w;

        *(float4*)&Bs[brow][bcol] =
            *(const float4*)(B + (size_t)(k0 + brow) * NDIM + cCol + bcol);
        __syncthreads();

        #pragma unroll
        for (int k = 0; k < BK; k++) {
            unsigned long long aP[8], bP[4];
            #pragma unroll
            for (int i = 0; i < 8; i++)
                aP[i] = *(const unsigned long long*)&As2[k][2 * (ty * 8 + i)];
            #pragma unroll
            for (int j = 0; j < 4; j++)
                bP[j] = *(const unsigned long long*)&Bs[k][tx * 8 + 2 * j];
            #pragma unroll
            for (int i = 0; i < 8; i++)
                #pragma unroll
                for (int j = 0; j < 4; j++)
                    ffma2(acc[i][j], aP[i], bP[j]);
        }
        __syncthreads();
    }

    #pragma unroll
    for (int i = 0; i < 8; i++) {
        int r = cRow + ty * 8 + i;
        if (r < N_NODES) {
            float f[8];
            #pragma unroll
            for (int j = 0; j < 4; j++) {
                unsigned int lo, hi;
                asm("mov.b64 {%0,%1}, %2;" : "=r"(lo), "=r"(hi) : "l"(acc[i][j]));
                f[2 * j]     = __uint_as_float(lo);
                f[2 * j + 1] = __uint_as_float(hi);
            }
            #pragma unroll
            for (int jj = 0; jj < 8; jj += 4) {
                int c = cCol + tx * 8 + jj;
                float4 v = make_float4(f[jj], f[jj + 1], f[jj + 2], f[jj + 3]);
                if (RELU_BIAS) {
                    const float4 bb = *(const float4*)(bias + c);
                    v.x = fmaxf(v.x + bb.x, 0.f);
                    v.y = fmaxf(v.y + bb.y, 0.f);
                    v.z = fmaxf(v.z + bb.z, 0.f);
                    v.w = fmaxf(v.w + bb.w, 0.f);
                }
                *(float4*)(C + (size_t)r * NDIM + c) = v;
            }
        }
    }
}

__global__ void __launch_bounds__(256) k_gemm1(const float* __restrict__ W1,
                                               const float* __restrict__ b1) {
    sgemm_body<IN_DIM, HID, true>((const float*)g_agg1, W1, b1, g_h1);
}

__global__ void __launch_bounds__(256) k_gemm2(const float* __restrict__ W2) {
    sgemm_body<HID, HID2, false>(g_h1, W2, nullptr, (float*)g_m2);
}

// ---------------- pooling ----------------
__global__ void k_zero_pool() {
    int i = blockIdx.x * blockDim.x + threadIdx.x;
    if (i < N_GRAPHS * HID2) g_pool[i] = 0.0f;
    if (i < N_GRAPHS) g_cnt[i] = 0.0f;
}

__global__ void k_pool(const void* __restrict__ batch, const float* __restrict__ b2) {
    int t = blockIdx.x * blockDim.x + threadIdx.x;
    if (t >= N_NODES * 32) return;
    int node = t >> 5;
    int j    = t & 31;
    int b    = get_idx(batch, node, g_idx64);
    if ((unsigned)b >= (unsigned)N_GRAPHS) return;
    float4 v  = g_agg2[t];
    float4 bb = ((const float4*)b2)[j];
    v.x = fmaxf(v.x + bb.x, 0.f);
    v.y = fmaxf(v.y + bb.y, 0.f);
    v.z = fmaxf(v.z + bb.z, 0.f);
    v.w = fmaxf(v.w + bb.w, 0.f);
    red_add_v4(&g_pool[b * HID2 + j * 4], v);
    if (j == 0) atomicAdd(&g_cnt[b], 1.0f);
}

__global__ void k_out(const float* __restrict__ Wfc, const float* __restrict__ bfc,
                      float* __restrict__ out) {
    int t = threadIdx.x;
    if (t >= N_GRAPHS * OUT_DIM) return;
    int g = t >> 2;
    int o = t & 3;
    float inv = 1.0f / fmaxf(g_cnt[g], 1.0f);
    float s = 0.0f;
    #pragma unroll 16
    for (int k = 0; k < HID2; k++)
        s = fmaf(g_pool[g * HID2 + k], Wfc[k * OUT_DIM + o], s);
    out[t] = s * inv + bfc[o];
}

// ---------------- launch ----------------
extern "C" void kernel_launch(void* const* d_in, const int* in_sizes, int n_in,
                              void* d_out, int out_size) {
    int ix = -1, isrc = -1, idst = -1, ibatch = -1, iW1 = -1, iW2 = -1;
    int ib1 = -1, ib2 = -1, iWfc = -1, ibfc = -1;
    for (int i = 0; i < n_in; i++) {
        int s = in_sizes[i];
        if      (s == N_NODES * IN_DIM)  ix = i;
        else if (s == N_EDGES)           { if (isrc < 0) isrc = i; else idst = i; }
        else if (s == N_NODES)           ibatch = i;
        else if (s == IN_DIM * HID)      { if (iW1 < 0) iW1 = i; else iW2 = i; }
        else if (s == HID)               ib1 = i;
        else if (s == HID2)              ib2 = i;
        else if (s == HID2 * OUT_DIM)    iWfc = i;
        else if (s == OUT_DIM)           ibfc = i;
    }
    if (in_sizes[0] != N_NODES * IN_DIM) { int tmp = isrc; isrc = idst; idst = tmp; }

    const float* x     = (const float*)d_in[ix];
    const void*  src   = d_in[isrc];
    const void*  dst   = d_in[idst];
    const void*  batch = d_in[ibatch];
    const float* W1    = (const float*)d_in[iW1];
    const float* b1    = (const float*)d_in[ib1];
    const float* W2    = (const float*)d_in[iW2];
    const float* b2    = (const float*)d_in[ib2];
    const float* Wfc   = (const float*)d_in[iWfc];
    const float* bfc   = (const float*)d_in[ibfc];
    float* out = (float*)d_out;

    const int TPB = 256;
    const int nodeBlocks  = (N_NODES + TPB - 1) / TPB;
    const int edgeBlocks  = (N_EDGES + TPB - 1) / TPB;
    const int nvecBlocks  = (N_NODES * 32 + TPB - 1) / TPB;
    const int evecBlocks  = (N_EDGES * 32 + TPB - 1) / TPB;

    k_detect<<<1, 32>>>((const int*)src);

    k_deg_init <<<nodeBlocks, TPB>>>();
    k_deg_count<<<edgeBlocks, TPB>>>(dst);
    k_rsqrt    <<<nodeBlocks, TPB>>>();

    // layer 1: aggregate x first (128-dim), then GEMM (+bias,relu)
    k_init_agg1<<<nvecBlocks, TPB>>>((const float4*)x);
    k_edge1    <<<evecBlocks, TPB>>>((const float4*)x, src, dst);
    {
        dim3 grid(HID / 128, (N_NODES + 127) / 128);
        k_gemm1<<<grid, 256>>>(W1, b1);
    }

    // layer 2: GEMM first (output 128-dim), then aggregate
    {
        dim3 grid(HID2 / 128, (N_NODES + 127) / 128);
        k_gemm2<<<grid, 256>>>(W2);
    }
    k_init_agg2<<<nvecBlocks, TPB>>>();
    k_edge2    <<<evecBlocks, TPB>>>(src, dst);

    // pool + fc
    k_zero_pool<<<(N_GRAPHS * HID2 + TPB - 1) / TPB, TPB>>>();
    k_pool     <<<nvecBlocks, TPB>>>(batch, b2);
    k_out      <<<1, N_GRAPHS * OUT_DIM>>>(Wfc, bfc, out);
}

// round 9
// speedup vs baseline: 1.4150x; 1.4150x over previous
#include <cuda_runtime.h>

// ---------------- problem constants ----------------
#define N_NODES  50000
#define N_EDGES  640000
#define N_GRAPHS 64
#define IN_DIM   128
#define HID      256
#define HID2     128   // HID/2
#define OUT_DIM  4

// ---------------- scratch (static device arrays; no allocation) ----------------
// RULE: these symbols are ONLY referenced inside device code; never passed as
// kernel arguments from host (host shadow address + ATS = silent wrong buffer).
__device__ float  g_dinv[N_NODES];                 // deg -> rsqrt(deg)
__device__ float4 g_agg1[N_NODES * (IN_DIM / 4)];  // aggregated x      [N,128]
__device__ float  g_h1 [N_NODES * HID];            // relu(agg1@W1+b1)  [N,256]
__device__ float4 g_m2  [N_NODES * (HID2 / 4)];    // h1@W2             [N,128]
__device__ float4 g_agg2[N_NODES * (HID2 / 4)];    // aggregated m2     [N,128]
__device__ float  g_pool[N_GRAPHS * HID2];         // per-graph sums
__device__ float  g_cnt [N_GRAPHS];                // per-graph counts
__device__ int    g_idx64;                         // 1 if index arrays are int64

// ---------------- helpers ----------------
__device__ __forceinline__ void red_add_v4(float* addr, float4 v) {
    asm volatile("red.global.add.v4.f32 [%0], {%1,%2,%3,%4};"
                 :: "l"(addr), "f"(v.x), "f"(v.y), "f"(v.z), "f"(v.w)
                 : "memory");
}

__device__ __forceinline__ int get_idx(const void* p, int i, int is64) {
    long long v;
    if (is64) v = __ldg(((const long long*)p) + i);
    else      v = __ldg(((const int*)p) + i);
    return (int)v;
}

__device__ __forceinline__ unsigned f2tf32(float f) {
    unsigned r;
    asm("cvt.rna.tf32.f32 %0, %1;" : "=r"(r) : "f"(f));
    return r;
}

// m16n8k8 tf32 MMA, fp32 accumulate (D += A*B), row.col
__device__ __forceinline__ void mma_tf32(float* d, const unsigned* a, const unsigned* b) {
    asm volatile(
        "mma.sync.aligned.m16n8k8.row.col.f32.tf32.tf32.f32 "
        "{%0,%1,%2,%3}, {%4,%5,%6,%7}, {%8,%9}, {%0,%1,%2,%3};"
        : "+f"(d[0]), "+f"(d[1]), "+f"(d[2]), "+f"(d[3])
        : "r"(a[0]), "r"(a[1]), "r"(a[2]), "r"(a[3]), "r"(b[0]), "r"(b[1]));
}

// ---------------- index dtype detection ----------------
__global__ void k_detect(const int* p) {
    int lane = threadIdx.x;
    int nz = 0;
    for (int i = lane; i < 4096; i += 32)
        if (p[2 * i + 1] != 0) nz = 1;
    unsigned m = __ballot_sync(0xffffffffu, nz);
    if (lane == 0) g_idx64 = (m == 0u) ? 1 : 0;
}

// ---------------- degree / norm ----------------
__global__ void k_deg_init() {
    int i = blockIdx.x * blockDim.x + threadIdx.x;
    if (i < N_NODES) g_dinv[i] = 1.0f;     // +1 self loop
}

__global__ void k_deg_count(const void* __restrict__ dst) {
    int e = blockIdx.x * blockDim.x + threadIdx.x;
    if (e < N_EDGES) {
        int d = get_idx(dst, e, g_idx64);
        if ((unsigned)d < (unsigned)N_NODES) atomicAdd(&g_dinv[d], 1.0f);
    }
}

__global__ void k_rsqrt() {
    int i = blockIdx.x * blockDim.x + threadIdx.x;
    if (i < N_NODES) g_dinv[i] = rsqrtf(g_dinv[i]);
}

// ---------------- aggregation init: agg = feat * dinv^2 (self-loop term) ----------------
__global__ void k_init_agg1(const float4* __restrict__ x) {
    int t = blockIdx.x * blockDim.x + threadIdx.x;     // node*32 + j
    if (t >= N_NODES * 32) return;
    int node = t >> 5;
    float di = g_dinv[node];
    float s = di * di;
    float4 v = x[t];
    v.x *= s; v.y *= s; v.z *= s; v.w *= s;
    g_agg1[t] = v;
}

__global__ void k_init_agg2() {
    int t = blockIdx.x * blockDim.x + threadIdx.x;
    if (t >= N_NODES * 32) return;
    int node = t >> 5;
    float di = g_dinv[node];
    float s = di * di;
    float4 v = g_m2[t];
    v.x *= s; v.y *= s; v.z *= s; v.w *= s;
    g_agg2[t] = v;
}

// ---------------- edge scatter: agg[dst] += feat[src]*dinv[s]*dinv[d] ----------------
__global__ void k_edge1(const float4* __restrict__ x,
                        const void* __restrict__ src, const void* __restrict__ dst) {
    int t = blockIdx.x * blockDim.x + threadIdx.x;
    int e = t >> 5;
    if (e >= N_EDGES) return;
    int is64 = g_idx64;
    int j = t & 31;
    int s = get_idx(src, e, is64);
    int d = get_idx(dst, e, is64);
    if ((unsigned)s >= (unsigned)N_NODES || (unsigned)d >= (unsigned)N_NODES) return;
    float norm = g_dinv[s] * g_dinv[d];
    float4 v = x[(size_t)s * 32 + j];
    v.x *= norm; v.y *= norm; v.z *= norm; v.w *= norm;
    red_add_v4((float*)(g_agg1 + (size_t)d * 32 + j), v);
}

__global__ void k_edge2(const void* __restrict__ src, const void* __restrict__ dst) {
    int t = blockIdx.x * blockDim.x + threadIdx.x;
    int e = t >> 5;
    if (e >= N_EDGES) return;
    int is64 = g_idx64;
    int j = t & 31;
    int s = get_idx(src, e, is64);
    int d = get_idx(dst, e, is64);
    if ((unsigned)s >= (unsigned)N_NODES || (unsigned)d >= (unsigned)N_NODES) return;
    float norm = g_dinv[s] * g_dinv[d];
    float4 v = g_m2[(size_t)s * 32 + j];
    v.x *= norm; v.y *= norm; v.z *= norm; v.w *= norm;
    red_add_v4((float*)(g_agg2 + (size_t)d * 32 + j), v);
}

// ---------------- GEMM via mma.sync m16n8k8 tf32 (fp32 accumulate) ----------------
// C[M,N] = A[M,K] @ B[K,N] (+bias,relu). BM=128, BN=128, BK=32.
// 256 threads = 8 warps in 4(m) x 2(n) layout; warp tile 32m x 64n
// (= 2 m16-tiles x 8 n8-tiles = 16 mma per k8 step).
// Operands converted to tf32 ONCE during global->shared staging.
// Shared strides padded (A:36, B:136) -> conflict-free fragment LDS.
template <int KDIM, int NDIM, bool RELU_BIAS>
__device__ __forceinline__ void gemm_mma_body(const float* __restrict__ A,
                                              const float* __restrict__ B,
                                              const float* __restrict__ bias,
                                              float* __restrict__ C) {
    constexpr int BM = 128, BN = 128, BK = 32;
    constexpr int ASTR = 36;    // padded stride (elements)
    constexpr int BSTR = 136;
    __shared__ unsigned As[BM * ASTR];   // [row][k], tf32
    __shared__ unsigned Bs[BK * BSTR];   // [k][col], tf32

    const int t    = threadIdx.x;
    const int lane = t & 31;
    const int w    = t >> 5;
    const int mw   = w & 3;          // 0..3
    const int nw   = w >> 2;         // 0..1
    const int g    = lane >> 2;      // groupID 0..7
    const int tg   = lane & 3;       // threadID-in-group 0..3
    const int cRow = blockIdx.y * BM;
    const int cCol = blockIdx.x * BN;

    float acc[2][8][4];
    #pragma unroll
    for (int mt = 0; mt < 2; mt++)
        #pragma unroll
        for (int nt = 0; nt < 8; nt++)
            #pragma unroll
            for (int i = 0; i < 4; i++) acc[mt][nt][i] = 0.0f;

    for (int k0 = 0; k0 < KDIM; k0 += BK) {
        // stage A tile: 128x32 floats = 1024 float4; 4 per thread
        #pragma unroll
        for (int i = 0; i < 4; i++) {
            int f   = t + 256 * i;          // 0..1023
            int row = f >> 3;                // /8 float4 per row
            int c4  = f & 7;
            float4 v = make_float4(0.f, 0.f, 0.f, 0.f);
            if (cRow + row < N_NODES)
                v = *(const float4*)(A + (size_t)(cRow + row) * KDIM + k0 + c4 * 4);
            uint4 u = make_uint4(f2tf32(v.x), f2tf32(v.y), f2tf32(v.z), f2tf32(v.w));
            *(uint4*)&As[row * ASTR + c4 * 4] = u;
        }
        // stage B tile: 32x128 floats = 1024 float4; 4 per thread
        #pragma unroll
        for (int i = 0; i < 4; i++) {
            int f   = t + 256 * i;
            int row = f >> 5;                // /32 float4 per row
            int c4  = f & 31;
            float4 v = *(const float4*)(B + (size_t)(k0 + row) * NDIM + cCol + c4 * 4);
            uint4 u = make_uint4(f2tf32(v.x), f2tf32(v.y), f2tf32(v.z), f2tf32(v.w));
            *(uint4*)&Bs[row * BSTR + c4 * 4] = u;
        }
        __syncthreads();

        #pragma unroll
        for (int kk = 0; kk < BK; kk += 8) {
            unsigned a[2][4];
            #pragma unroll
            for (int mt = 0; mt < 2; mt++) {
                int r0 = mw * 32 + mt * 16 + g;
                a[mt][0] = As[r0 * ASTR + kk + tg];
                a[mt][1] = As[(r0 + 8) * ASTR + kk + tg];
                a[mt][2] = As[r0 * ASTR + kk + tg + 4];
                a[mt][3] = As[(r0 + 8) * ASTR + kk + tg + 4];
            }
            #pragma unroll
            for (int nt = 0; nt < 8; nt++) {
                unsigned b[2];
                int c0 = nw * 64 + nt * 8 + g;
                b[0] = Bs[(kk + tg)     * BSTR + c0];
                b[1] = Bs[(kk + tg + 4) * BSTR + c0];
                mma_tf32(acc[0][nt], a[0], b);
                mma_tf32(acc[1][nt], a[1], b);
            }
        }
        __syncthreads();
    }

    // epilogue: c0,c1 at (r, 2tg..2tg+1), c2,c3 at (r+8, same cols)
    #pragma unroll
    for (int mt = 0; mt < 2; mt++) {
        int rBase = cRow + mw * 32 + mt * 16 + g;
        #pragma unroll
        for (int nt = 0; nt < 8; nt++) {
            int c = cCol + nw * 64 + nt * 8 + 2 * tg;
            float2 lo = make_float2(acc[mt][nt][0], acc[mt][nt][1]);
            float2 hi = make_float2(acc[mt][nt][2], acc[mt][nt][3]);
            if (RELU_BIAS) {
                float2 bb = *(const float2*)(bias + c);
                lo.x = fmaxf(lo.x + bb.x, 0.f); lo.y = fmaxf(lo.y + bb.y, 0.f);
                hi.x = fmaxf(hi.x + bb.x, 0.f); hi.y = fmaxf(hi.y + bb.y, 0.f);
            }
            if (rBase < N_NODES)
                *(float2*)(C + (size_t)rBase * NDIM + c) = lo;
            if (rBase + 8 < N_NODES)
                *(float2*)(C + (size_t)(rBase + 8) * NDIM + c) = hi;
        }
    }
}

__global__ void __launch_bounds__(256) k_gemm1(const float* __restrict__ W1,
                                               const float* __restrict__ b1) {
    gemm_mma_body<IN_DIM, HID, true>((const float*)g_agg1, W1, b1, g_h1);
}

__global__ void __launch_bounds__(256) k_gemm2(const float* __restrict__ W2) {
    gemm_mma_body<HID, HID2, false>(g_h1, W2, nullptr, (float*)g_m2);
}

// ---------------- pooling ----------------
__global__ void k_zero_pool() {
    int i = blockIdx.x * blockDim.x + threadIdx.x;
    if (i < N_GRAPHS * HID2) g_pool[i] = 0.0f;
    if (i < N_GRAPHS) g_cnt[i] = 0.0f;
}

__global__ void k_pool(const void* __restrict__ batch, const float* __restrict__ b2) {
    int t = blockIdx.x * blockDim.x + threadIdx.x;
    if (t >= N_NODES * 32) return;
    int node = t >> 5;
    int j    = t & 31;
    int b    = get_idx(batch, node, g_idx64);
    if ((unsigned)b >= (unsigned)N_GRAPHS) return;
    float4 v  = g_agg2[t];
    float4 bb = ((const float4*)b2)[j];
    v.x = fmaxf(v.x + bb.x, 0.f);
    v.y = fmaxf(v.y + bb.y, 0.f);
    v.z = fmaxf(v.z + bb.z, 0.f);
    v.w = fmaxf(v.w + bb.w, 0.f);
    red_add_v4(&g_pool[b * HID2 + j * 4], v);
    if (j == 0) atomicAdd(&g_cnt[b], 1.0f);
}

__global__ void k_out(const float* __restrict__ Wfc, const float* __restrict__ bfc,
                      float* __restrict__ out) {
    int t = threadIdx.x;
    if (t >= N_GRAPHS * OUT_DIM) return;
    int g = t >> 2;
    int o = t & 3;
    float inv = 1.0f / fmaxf(g_cnt[g], 1.0f);
    float s = 0.0f;
    #pragma unroll 16
    for (int k = 0; k < HID2; k++)
        s = fmaf(g_pool[g * HID2 + k], Wfc[k * OUT_DIM + o], s);
    out[t] = s * inv + bfc[o];
}

// ---------------- launch ----------------
extern "C" void kernel_launch(void* const* d_in, const int* in_sizes, int n_in,
                              void* d_out, int out_size) {
    int ix = -1, isrc = -1, idst = -1, ibatch = -1, iW1 = -1, iW2 = -1;
    int ib1 = -1, ib2 = -1, iWfc = -1, ibfc = -1;
    for (int i = 0; i < n_in; i++) {
        int s = in_sizes[i];
        if      (s == N_NODES * IN_DIM)  ix = i;
        else if (s == N_EDGES)           { if (isrc < 0) isrc = i; else idst = i; }
        else if (s == N_NODES)           ibatch = i;
        else if (s == IN_DIM * HID)      { if (iW1 < 0) iW1 = i; else iW2 = i; }
        else if (s == HID)               ib1 = i;
        else if (s == HID2)              ib2 = i;
        else if (s == HID2 * OUT_DIM)    iWfc = i;
        else if (s == OUT_DIM)           ibfc = i;
    }
    if (in_sizes[0] != N_NODES * IN_DIM) { int tmp = isrc; isrc = idst; idst = tmp; }

    const float* x     = (const float*)d_in[ix];
    const void*  src   = d_in[isrc];
    const void*  dst   = d_in[idst];
    const void*  batch = d_in[ibatch];
    const float* W1    = (const float*)d_in[iW1];
    const float* b1    = (const float*)d_in[ib1];
    const float* W2    = (const float*)d_in[iW2];
    const float* b2    = (const float*)d_in[ib2];
    const float* Wfc   = (const float*)d_in[iWfc];
    const float* bfc   = (const float*)d_in[ibfc];
    float* out = (float*)d_out;

    const int TPB = 256;
    const int nodeBlocks  = (N_NODES + TPB - 1) / TPB;
    const int edgeBlocks  = (N_EDGES + TPB - 1) / TPB;
    const int nvecBlocks  = (N_NODES * 32 + TPB - 1) / TPB;
    const int evecBlocks  = (N_EDGES * 32 + TPB - 1) / TPB;

    k_detect<<<1, 32>>>((const int*)src);

    k_deg_init <<<nodeBlocks, TPB>>>();
    k_deg_count<<<edgeBlocks, TPB>>>(dst);
    k_rsqrt    <<<nodeBlocks, TPB>>>();

    // layer 1: aggregate x first (128-dim), then GEMM (+bias,relu)
    k_init_agg1<<<nvecBlocks, TPB>>>((const float4*)x);
    k_edge1    <<<evecBlocks, TPB>>>((const float4*)x, src, dst);
    {
        dim3 grid(HID / 128, (N_NODES + 127) / 128);
        k_gemm1<<<grid, 256>>>(W1, b1);
    }

    // layer 2: GEMM first (output 128-dim), then aggregate
    {
        dim3 grid(HID2 / 128, (N_NODES + 127) / 128);
        k_gemm2<<<grid, 256>>>(W2);
    }
    k_init_agg2<<<nvecBlocks, TPB>>>();
    k_edge2    <<<evecBlocks, TPB>>>(src, dst);

    // pool + fc
    k_zero_pool<<<(N_GRAPHS * HID2 + TPB - 1) / TPB, TPB>>>();
    k_pool     <<<nvecBlocks, TPB>>>(batch, b2);
    k_out      <<<1, N_GRAPHS * OUT_DIM>>>(Wfc, bfc, out);
}